// round 14
// baseline (speedup 1.0000x reference)
#include <cuda_runtime.h>
#include <cuda_fp16.h>
#include <cuda_fp8.h>
#include <math.h>

#define B_ 256
#define L_ 196
#define D_ 512
#define H_ 1024
#define E_ 512
#define V_ 10000
#define T_ 20

// ---------------- persistent device scratch ----------------
__device__ __half g_feat16[B_ * L_ * D_];            // fp16 features (ctx GEMM A)
__device__ unsigned char g_feat8[B_ * L_ * D_];      // fp8 features (attention pass2)
__device__ __half g_ctx16 [B_ * L_ * D_];            // fp16 ctx_enc (attention pass1)
__device__ __half g_WtImg [D_ * D_];                 // image_att_w transposed [e][d]
__device__ __half g_AttHH [D_ * H_];                 // att_hh_w [n=512][k=1024]
__device__ __half g_InitH [H_ * D_];
__device__ __half g_InitC [H_ * D_];
__device__ __half g_Wcat  [4 * H_ * 2 * H_];         // reordered rows n'=4j+g
__device__ float  g_biasSum[4 * H_];                 // reordered b_ih+b_hh
__device__ __half g_embAll[T_ * B_ * E_];            // [t][b][e]
__device__ __half g_fmean16[B_ * D_];
__device__ __half g_hproj16[B_ * D_];                // fp16 hproj (attention input)
__device__ __half g_xcat   [B_ * 2048];              // [emb | context | h]
__device__ float  g_cstate [B_ * H_];

// ---------------- helpers ----------------
__device__ __forceinline__ float tanh_precise(float x) {
    float ax = fabsf(x);
    float t = __expf(-2.f * ax);
    float r = (1.f - t) / (1.f + t);
    return copysignf(r, x);
}
__device__ __forceinline__ float sigmoid_f(float x) { return 1.f / (1.f + __expf(-x)); }
__device__ __forceinline__ unsigned char f2e4m3(float x) {
    return (unsigned char)__nv_cvt_float_to_fp8(x, __NV_SATFINITE, __NV_E4M3);
}
__device__ __forceinline__ float2 fp8x2_to_f2(unsigned short s) {
    __half2_raw hr = __nv_cvt_fp8x2_to_halfraw2((__nv_fp8x2_storage_t)s, __NV_E4M3);
    __half2 h = *reinterpret_cast<__half2*>(&hr);
    return __half22float2(h);
}
__device__ __forceinline__ __half2 htanh2(__half2 x) {
    unsigned u = *(unsigned*)&x, r;
    asm("tanh.approx.f16x2 %0, %1;" : "=r"(r) : "r"(u));
    return *(__half2*)&r;
}
__device__ __forceinline__ void cp16(const void* smem_dst, const void* gmem_src) {
    unsigned s = (unsigned)__cvta_generic_to_shared(smem_dst);
    asm volatile("cp.async.cg.shared.global [%0], [%1], 16;\n" :: "r"(s), "l"(gmem_src));
}
__device__ __forceinline__ void cp_commit() { asm volatile("cp.async.commit_group;\n"); }
__device__ __forceinline__ void mma16816(float* c, const unsigned* a, const unsigned* b) {
    asm volatile(
        "mma.sync.aligned.m16n8k16.row.col.f32.f16.f16.f32 "
        "{%0,%1,%2,%3},{%4,%5,%6,%7},{%8,%9},{%0,%1,%2,%3};\n"
        : "+f"(c[0]), "+f"(c[1]), "+f"(c[2]), "+f"(c[3])
        : "r"(a[0]), "r"(a[1]), "r"(a[2]), "r"(a[3]), "r"(b[0]), "r"(b[1]));
}
// ldmatrix x4: 16x16 A tile (row-major, ld in halves), regs in mma A-fragment order
__device__ __forceinline__ void ldm_a(unsigned* r, const __half* base, int ld) {
    int lane = threadIdx.x & 31;
    int sel = lane >> 3, lr = lane & 7;
    const __half* p = base + ((sel & 1) * 8 + lr) * ld + (sel >> 1) * 8;
    unsigned a = (unsigned)__cvta_generic_to_shared(p);
    asm volatile("ldmatrix.sync.aligned.m8n8.x4.shared.b16 {%0,%1,%2,%3}, [%4];"
                 : "=r"(r[0]), "=r"(r[1]), "=r"(r[2]), "=r"(r[3]) : "r"(a));
}
// ldmatrix x4: 16(n)x16(k) B tile
__device__ __forceinline__ void ldm_b(unsigned* r, const __half* base, int ld) {
    int lane = threadIdx.x & 31;
    int sel = lane >> 3, lr = lane & 7;
    const __half* p = base + ((sel >> 1) * 8 + lr) * ld + (sel & 1) * 8;
    unsigned a = (unsigned)__cvta_generic_to_shared(p);
    asm volatile("ldmatrix.sync.aligned.m8n8.x4.shared.b16 {%0,%1,%2,%3}, [%4];"
                 : "=r"(r[0]), "=r"(r[1]), "=r"(r[2]), "=r"(r[3]) : "r"(a));
}

// ---------------- prep kernels (one-time) ----------------
__global__ void prep_kernel(const float* __restrict__ img_w,
                            const float* __restrict__ att_hh_w,
                            const float* __restrict__ init_h_w,
                            const float* __restrict__ init_c_w,
                            const float* __restrict__ W_ih,
                            const float* __restrict__ W_hh,
                            const float* __restrict__ b_ih,
                            const float* __restrict__ b_hh,
                            const int*   __restrict__ captions,
                            const float* __restrict__ embedding) {
    const long n_wt   = (long)D_ * D_;
    const long n_att  = (long)D_ * H_;
    const long n_init = (long)H_ * D_;
    const long n_wcat = 4096L * 2048L;
    const long n_bias = 4096;
    const long n_emb  = (long)T_ * B_ * E_;
    const long total  = n_wt + n_att + 2 * n_init + n_wcat + n_bias + n_emb;
    long stride = (long)gridDim.x * blockDim.x;
    for (long idx = (long)blockIdx.x * blockDim.x + threadIdx.x; idx < total; idx += stride) {
        long i = idx;
        if (i < n_wt) {
            long e = i / D_, d = i % D_;
            g_WtImg[i] = __float2half(img_w[d * D_ + e]);
            continue;
        }
        i -= n_wt;
        if (i < n_att) { g_AttHH[i] = __float2half(att_hh_w[i]); continue; }
        i -= n_att;
        if (i < n_init) { g_InitH[i] = __float2half(init_h_w[i]); continue; }
        i -= n_init;
        if (i < n_init) { g_InitC[i] = __float2half(init_c_w[i]); continue; }
        i -= n_init;
        if (i < n_wcat) {
            long np = i >> 11, k = i & 2047;
            long j = np >> 2, g = np & 3;
            long orig = g * 1024 + j;
            g_Wcat[i] = __float2half(k < H_ ? W_ih[orig * H_ + k] : W_hh[orig * H_ + (k - H_)]);
            continue;
        }
        i -= n_wcat;
        if (i < n_bias) {
            long j = i >> 2, g = i & 3;
            long orig = g * 1024 + j;
            g_biasSum[i] = b_ih[orig] + b_hh[orig];
            continue;
        }
        i -= n_bias;
        {
            long t = i / ((long)B_ * E_);
            long r = i % ((long)B_ * E_);
            long b = r / E_, e = r % E_;
            int cap = captions[b * T_ + t];
            g_embAll[i] = __float2half(embedding[(long)cap * E_ + e]);
        }
    }
}

__global__ void conv_feat_kernel(const float* __restrict__ f) {
    const long n2 = (long)B_ * L_ * D_ / 2;
    const float2* f2 = (const float2*)f;
    __half2* o2 = (__half2*)g_feat16;
    long stride = (long)gridDim.x * blockDim.x;
    for (long i = (long)blockIdx.x * blockDim.x + threadIdx.x; i < n2; i += stride) {
        float2 v = f2[i];
        o2[i] = __floats2half2_rn(v.x, v.y);
        g_feat8[i * 2]     = f2e4m3(v.x);
        g_feat8[i * 2 + 1] = f2e4m3(v.y);
    }
}

// fmean from fp16 features (conv_feat runs first; stream-ordered)
__global__ void fmean_kernel() {
    int b = blockIdx.x;
    int d = threadIdx.x;  // 512 threads
    const __half* p = g_feat16 + (long)b * L_ * D_ + d;
    float acc = 0.f;
#pragma unroll 4
    for (int l = 0; l < L_; l++) acc += __half2float(p[(long)l * D_]);
    g_fmean16[b * D_ + d] = __float2half(acc * (1.0f / L_));
}

// ---------------- BK64/S2 GEMM (ctx only; output fp16) ----------------
#define GSMEM (2 * (64 + 128) * 72 * 2)
__global__ void __launch_bounds__(256) gemm64_ctx(
    const __half* __restrict__ A, int lda,
    const __half* __restrict__ Bm, int ldb,
    __half* __restrict__ Ch, int ldc, int K) {
    extern __shared__ __align__(16) char dynsm[];
    __half* As = (__half*)dynsm;          // [2][64][72]
    __half* Bs = As + 2 * 64 * 72;        // [2][128][72]
    const int AST = 64 * 72, BST = 128 * 72;

    int tid = threadIdx.x;
    int lane = tid & 31, warp = tid >> 5;
    int wm = warp & 1, wn = warp >> 1;
    int bm = blockIdx.y, bn = blockIdx.x;

    int rowA = tid >> 3, ch = (tid & 7) * 8;
    const __half* gA0 = A + ((long)bm * 64 + rowA) * lda + ch;
    const __half* gA1 = gA0 + 32L * lda;
    const __half* gB0 = Bm + ((long)bn * 128 + rowA) * ldb + ch;

    float acc[2][4][4];
#pragma unroll
    for (int mi = 0; mi < 2; mi++)
#pragma unroll
        for (int ni = 0; ni < 4; ni++)
#pragma unroll
            for (int q = 0; q < 4; q++) acc[mi][ni][q] = 0.f;

    const int KT = K >> 6;
    cp16(As + rowA * 72 + ch, gA0);
    cp16(As + (rowA + 32) * 72 + ch, gA1);
#pragma unroll
    for (int q = 0; q < 4; q++)
        cp16(Bs + (rowA + q * 32) * 72 + ch, gB0 + (long)q * 32 * ldb);
    cp_commit();

    int agrp = lane >> 2, atg = lane & 3;

    for (int kt = 0; kt < KT; kt++) {
        asm volatile("cp.async.wait_group 0;\n");
        __syncthreads();
        int cur = kt & 1;
        int nxt = kt + 1;
        if (nxt < KT) {
            int nb = nxt & 1;
            int k0 = nxt * 64;
            cp16(As + nb * AST + rowA * 72 + ch, gA0 + k0);
            cp16(As + nb * AST + (rowA + 32) * 72 + ch, gA1 + k0);
#pragma unroll
            for (int q = 0; q < 4; q++)
                cp16(Bs + nb * BST + (rowA + q * 32) * 72 + ch, gB0 + (long)q * 32 * ldb + k0);
            cp_commit();
        }
        __half* cA = As + cur * AST;
        __half* cB = Bs + cur * BST;
#pragma unroll
        for (int kk = 0; kk < 64; kk += 16) {
            unsigned afr[2][4], tb[4], bfr[4][2];
            ldm_a(afr[0], cA + (wm * 32) * 72 + kk, 72);
            ldm_a(afr[1], cA + (wm * 32 + 16) * 72 + kk, 72);
            ldm_b(tb, cB + (wn * 32) * 72 + kk, 72);
            bfr[0][0] = tb[0]; bfr[0][1] = tb[1]; bfr[1][0] = tb[2]; bfr[1][1] = tb[3];
            ldm_b(tb, cB + (wn * 32 + 16) * 72 + kk, 72);
            bfr[2][0] = tb[0]; bfr[2][1] = tb[1]; bfr[3][0] = tb[2]; bfr[3][1] = tb[3];
#pragma unroll
            for (int mi = 0; mi < 2; mi++)
#pragma unroll
                for (int ni = 0; ni < 4; ni++) mma16816(acc[mi][ni], afr[mi], bfr[ni]);
        }
    }

#pragma unroll
    for (int mi = 0; mi < 2; mi++) {
#pragma unroll
        for (int ni = 0; ni < 4; ni++) {
            int row = bm * 64 + wm * 32 + mi * 16 + agrp;
            int col = bn * 128 + wn * 32 + ni * 8 + atg * 2;
            Ch[(long)row * ldc + col]           = __float2half(acc[mi][ni][0]);
            Ch[(long)row * ldc + col + 1]       = __float2half(acc[mi][ni][1]);
            Ch[(long)(row + 8) * ldc + col]     = __float2half(acc[mi][ni][2]);
            Ch[(long)(row + 8) * ldc + col + 1] = __float2half(acc[mi][ni][3]);
        }
    }
}

// ---------------- BK32/S3 GEMM (h0/c0), R7-proven numerics ----------------
// OUT: 0 = fp32 Cf, 1 = fp16 Ch
template <int OUT>
__global__ void __launch_bounds__(256) gemm32_f16(
    const __half* __restrict__ A, int lda,
    const __half* __restrict__ Bm, int ldb,
    const float* __restrict__ bias,
    float* __restrict__ Cf, __half* __restrict__ Ch, int ldc, int K) {
    const int S = 3;
    __shared__ __align__(16) __half As[S][64][40];
    __shared__ __align__(16) __half Bs[S][128][40];

    int tid = threadIdx.x;
    int lane = tid & 31, warp = tid >> 5;
    int wm = warp & 1, wn = warp >> 1;
    int bm = blockIdx.y, bn = blockIdx.x;

    const __half* gA  = A  + ((long)bm * 64  + (tid >> 2)) * lda + (tid & 3) * 8;
    const __half* gB0 = Bm + ((long)bn * 128 + (tid >> 2)) * ldb + (tid & 3) * 8;
    const __half* gB1 = gB0 + 64L * ldb;

    __half* sA  = &As[0][tid >> 2][(tid & 3) * 8];
    __half* sB0 = &Bs[0][tid >> 2][(tid & 3) * 8];
    __half* sB1 = sB0 + 64 * 40;
    const int ABUF = 64 * 40;
    const int BBUF = 128 * 40;

    float acc[2][4][4];
#pragma unroll
    for (int mi = 0; mi < 2; mi++)
#pragma unroll
        for (int ni = 0; ni < 4; ni++)
#pragma unroll
            for (int q = 0; q < 4; q++) acc[mi][ni][q] = 0.f;

    const int KT = K >> 5;
#pragma unroll
    for (int s = 0; s < S - 1; s++) {
        if (s < KT) {
            cp16(sA + s * ABUF, gA + s * 32);
            cp16(sB0 + s * BBUF, gB0 + s * 32);
            cp16(sB1 + s * BBUF, gB1 + s * 32);
        }
        cp_commit();
    }

    int agrp = lane >> 2, atg = lane & 3;

    for (int kt = 0; kt < KT; kt++) {
        asm volatile("cp.async.wait_group %0;\n" :: "n"(S - 2));
        __syncthreads();
        int nxt = kt + S - 1;
        if (nxt < KT) {
            int nb = nxt % S;
            cp16(sA + nb * ABUF, gA + nxt * 32);
            cp16(sB0 + nb * BBUF, gB0 + nxt * 32);
            cp16(sB1 + nb * BBUF, gB1 + nxt * 32);
        }
        cp_commit();
        int cur = kt % S;
#pragma unroll
        for (int kk = 0; kk < 32; kk += 16) {
            unsigned afr[2][4], tb[4], bfr[4][2];
            ldm_a(afr[0], &As[cur][wm * 32][kk], 40);
            ldm_a(afr[1], &As[cur][wm * 32 + 16][kk], 40);
            ldm_b(tb, &Bs[cur][wn * 32][kk], 40);
            bfr[0][0] = tb[0]; bfr[0][1] = tb[1]; bfr[1][0] = tb[2]; bfr[1][1] = tb[3];
            ldm_b(tb, &Bs[cur][wn * 32 + 16][kk], 40);
            bfr[2][0] = tb[0]; bfr[2][1] = tb[1]; bfr[3][0] = tb[2]; bfr[3][1] = tb[3];
#pragma unroll
            for (int mi = 0; mi < 2; mi++)
#pragma unroll
                for (int ni = 0; ni < 4; ni++) mma16816(acc[mi][ni], afr[mi], bfr[ni]);
        }
    }

#pragma unroll
    for (int mi = 0; mi < 2; mi++) {
#pragma unroll
        for (int ni = 0; ni < 4; ni++) {
            int row = bm * 64 + wm * 32 + mi * 16 + agrp;
            int col = bn * 128 + wn * 32 + ni * 8 + atg * 2;
            float bv0 = bias ? bias[col] : 0.f;
            float bv1 = bias ? bias[col + 1] : 0.f;
            float v00 = acc[mi][ni][0] + bv0, v01 = acc[mi][ni][1] + bv1;
            float v10 = acc[mi][ni][2] + bv0, v11 = acc[mi][ni][3] + bv1;
            if (OUT == 1) {
                Ch[(long)row * ldc + col]           = __float2half(v00);
                Ch[(long)row * ldc + col + 1]       = __float2half(v01);
                Ch[(long)(row + 8) * ldc + col]     = __float2half(v10);
                Ch[(long)(row + 8) * ldc + col + 1] = __float2half(v11);
            } else {
                Cf[(long)row * ldc + col]           = v00;
                Cf[(long)row * ldc + col + 1]       = v01;
                Cf[(long)(row + 8) * ldc + col]     = v10;
                Cf[(long)(row + 8) * ldc + col + 1] = v11;
            }
        }
    }
}

// ---------------- hproj: [256,512] = h @ AttHH^T + b -> fp16 ; 64 CTAs, tile 16x128 ----------------
__global__ void __launch_bounds__(256) hproj_kernel(const float* __restrict__ att_b) {
    const int LDSH = 72;
    __shared__ __align__(16) __half hA[2][16][LDSH];
    __shared__ __align__(16) __half hB[2][128][LDSH];
    int tid = threadIdx.x;
    int lane = tid & 31, warp = tid >> 5;
    int cta = blockIdx.x;
    int m0 = (cta >> 2) * 16, n0 = (cta & 3) * 128;

    float acc[2][4];
#pragma unroll
    for (int ni = 0; ni < 2; ni++)
#pragma unroll
        for (int q = 0; q < 4; q++) acc[ni][q] = 0.f;

    const __half* gA = g_xcat + (m0 + (tid >> 3)) * 2048 + 1024 + (tid & 7) * 8;  // tid<128
    const int KT = 1024 / 64;
    if (tid < 128) cp16(&hA[0][tid >> 3][(tid & 7) * 8], gA);
#pragma unroll
    for (int q = 0; q < 4; q++) {
        int idx = tid + 256 * q;
        int row = idx >> 3, ch = idx & 7;
        cp16(&hB[0][row][ch * 8], g_AttHH + (n0 + row) * 1024 + ch * 8);
    }
    cp_commit();

    for (int kt = 0; kt < KT; kt++) {
        asm volatile("cp.async.wait_group 0;\n");
        __syncthreads();
        int cur = kt & 1;
        int nxt = kt + 1;
        if (nxt < KT) {
            int nb = nxt & 1;
            if (tid < 128) cp16(&hA[nb][tid >> 3][(tid & 7) * 8], gA + nxt * 64);
#pragma unroll
            for (int q = 0; q < 4; q++) {
                int idx = tid + 256 * q;
                int row = idx >> 3, ch = idx & 7;
                cp16(&hB[nb][row][ch * 8], g_AttHH + (n0 + row) * 1024 + nxt * 64 + ch * 8);
            }
        }
        cp_commit();
#pragma unroll
        for (int kk = 0; kk < 64; kk += 16) {
            unsigned afr[4], tb[4], bfr[2][2];
            ldm_a(afr, &hA[cur][0][kk], LDSH);
            ldm_b(tb, &hB[cur][warp * 16][kk], LDSH);
            bfr[0][0] = tb[0]; bfr[0][1] = tb[1]; bfr[1][0] = tb[2]; bfr[1][1] = tb[3];
            mma16816(acc[0], afr, bfr[0]);
            mma16816(acc[1], afr, bfr[1]);
        }
        __syncthreads();
    }
    int r = lane >> 2, cf = (lane & 3) * 2;
#pragma unroll
    for (int ni = 0; ni < 2; ni++) {
        int n = n0 + warp * 16 + ni * 8 + cf;
        float b0 = att_b[n], b1 = att_b[n + 1];
        g_hproj16[(m0 + r) * 512 + n]         = __float2half(acc[ni][0] + b0);
        g_hproj16[(m0 + r) * 512 + n + 1]     = __float2half(acc[ni][1] + b1);
        g_hproj16[(m0 + r + 8) * 512 + n]     = __float2half(acc[ni][2] + b0);
        g_hproj16[(m0 + r + 8) * 512 + n + 1] = __float2half(acc[ni][3] + b1);
    }
}

// ---------------- attention: f16x2 score pass (fp16 ctx) + fp8/fp32 context pass ----------------
__global__ void __launch_bounds__(256) attention_kernel(const float* __restrict__ watt, int t) {
    int b = blockIdx.x;
    int tid = threadIdx.x, lane = tid & 31, warp = tid >> 5;
    __shared__ float sc[L_], alph[L_], red[256];

    // copy this step's embedding into xcat emb slice
    {
        const __half* src = g_embAll + ((long)t * B_ + b) * E_;
        for (int k = tid; k < E_; k += 256) g_xcat[b * 2048 + k] = src[k];
    }

    // per-lane fixed 16-d slice as half2 pairs
    __half2 hp2[8], w2[8];
    {
        const __half2* hpp = (const __half2*)(g_hproj16 + b * D_ + lane * 16);
#pragma unroll
        for (int q = 0; q < 8; q++) {
            hp2[q] = hpp[q];
            int d = lane * 16 + q * 2;
            w2[q] = __floats2half2_rn(watt[d], watt[d + 1]);
        }
    }

    // pass 1: scores over L — HADD2 + tanh.f16x2 + HFMA2, fp32 flush per l
    const uint4* crow = (const uint4*)(g_ctx16 + (long)b * L_ * D_);
    for (int l = warp; l < L_; l += 8) {
        const uint4* cr = crow + l * (D_ / 8) + lane * 2;
        uint4 u0 = cr[0], u1 = cr[1];
        const __half2* c0 = (const __half2*)&u0;
        const __half2* c1 = (const __half2*)&u1;
        __half2 a2 = __float2half2_rn(0.f);
#pragma unroll
        for (int q = 0; q < 4; q++)
            a2 = __hfma2(htanh2(__hadd2(c0[q], hp2[q])), w2[q], a2);
#pragma unroll
        for (int q = 0; q < 4; q++)
            a2 = __hfma2(htanh2(__hadd2(c1[q], hp2[q + 4])), w2[q + 4], a2);
        float2 fr = __half22float2(a2);
        float acc = fr.x + fr.y;
#pragma unroll
        for (int o = 16; o; o >>= 1) acc += __shfl_xor_sync(0xffffffffu, acc, o);
        if (lane == 0) sc[l] = acc;
    }
    __syncthreads();

    // softmax over L (fp32)
    float v = (tid < L_) ? sc[tid] : -3e38f;
    red[tid] = v;
    __syncthreads();
#pragma unroll
    for (int s = 128; s; s >>= 1) {
        if (tid < s) red[tid] = fmaxf(red[tid], red[tid + s]);
        __syncthreads();
    }
    float mx = red[0];
    __syncthreads();
    float e = (tid < L_) ? __expf(v - mx) : 0.f;
    red[tid] = e;
    __syncthreads();
#pragma unroll
    for (int s = 128; s; s >>= 1) {
        if (tid < s) red[tid] += red[tid + s];
        __syncthreads();
    }
    float inv = 1.f / red[0];
    if (tid < L_) alph[tid] = e * inv;
    __syncthreads();

    // pass 2: context from fp8 features (fp32 accumulation — proven path)
    const unsigned char* fbase = g_feat8 + (long)b * L_ * D_ + tid * 2;
    float a0 = 0.f, a1 = 0.f;
#pragma unroll 4
    for (int l = 0; l < L_; l++) {
        unsigned short u = *(const unsigned short*)(fbase + (long)l * D_);
        float2 f2 = fp8x2_to_f2(u);
        float al = alph[l];
        a0 = fmaf(al, f2.x, a0);
        a1 = fmaf(al, f2.y, a1);
    }
    __half* dst = g_xcat + b * 2048 + 512 + tid * 2;
    dst[0] = __float2half(a0 * (1.0f / L_));
    dst[1] = __float2half(a1 * (1.0f / L_));
}

// ---------------- gates GEMM [256,4096] K=2048, BK32/S3 + fused LSTM (R7-proven) ----------------
__global__ void __launch_bounds__(256) gates_lstm_kernel(
    const int* __restrict__ masks, float* __restrict__ out, int t) {
    const int S = 3;
    __shared__ __align__(16) __half As[S][64][40];
    __shared__ __align__(16) __half Bs[S][128][40];

    int tid = threadIdx.x;
    int lane = tid & 31, warp = tid >> 5;
    int wm = warp & 1, wn = warp >> 1;
    int bm = blockIdx.y, bn = blockIdx.x;
    const int K = 2048;

    const __half* gA  = g_xcat + ((long)bm * 64  + (tid >> 2)) * 2048 + (tid & 3) * 8;
    const __half* gB0 = g_Wcat + ((long)bn * 128 + (tid >> 2)) * 2048 + (tid & 3) * 8;
    const __half* gB1 = gB0 + 64L * 2048;

    __half* sA  = &As[0][tid >> 2][(tid & 3) * 8];
    __half* sB0 = &Bs[0][tid >> 2][(tid & 3) * 8];
    __half* sB1 = sB0 + 64 * 40;
    const int ABUF = 64 * 40;
    const int BBUF = 128 * 40;

    float acc[2][4][4];
#pragma unroll
    for (int mi = 0; mi < 2; mi++)
#pragma unroll
        for (int ni = 0; ni < 4; ni++)
#pragma unroll
            for (int q = 0; q < 4; q++) acc[mi][ni][q] = 0.f;

    const int KT = K >> 5;
#pragma unroll
    for (int s = 0; s < S - 1; s++) {
        cp16(sA + s * ABUF, gA + s * 32);
        cp16(sB0 + s * BBUF, gB0 + s * 32);
        cp16(sB1 + s * BBUF, gB1 + s * 32);
        cp_commit();
    }

    int agrp = lane >> 2, atg = lane & 3;

    for (int kt = 0; kt < KT; kt++) {
        asm volatile("cp.async.wait_group %0;\n" :: "n"(S - 2));
        __syncthreads();
        int nxt = kt + S - 1;
        if (nxt < KT) {
            int nb = nxt % S;
            cp16(sA + nb * ABUF, gA + nxt * 32);
            cp16(sB0 + nb * BBUF, gB0 + nxt * 32);
            cp16(sB1 + nb * BBUF, gB1 + nxt * 32);
        }
        cp_commit();
        int cur = kt % S;
#pragma unroll
        for (int kk = 0; kk < 32; kk += 16) {
            unsigned afr[2][4], tb[4], bfr[4][2];
            ldm_a(afr[0], &As[cur][wm * 32][kk], 40);
            ldm_a(afr[1], &As[cur][wm * 32 + 16][kk], 40);
            ldm_b(tb, &Bs[cur][wn * 32][kk], 40);
            bfr[0][0] = tb[0]; bfr[0][1] = tb[1]; bfr[1][0] = tb[2]; bfr[1][1] = tb[3];
            ldm_b(tb, &Bs[cur][wn * 32 + 16][kk], 40);
            bfr[2][0] = tb[0]; bfr[2][1] = tb[1]; bfr[3][0] = tb[2]; bfr[3][1] = tb[3];
#pragma unroll
            for (int mi = 0; mi < 2; mi++)
#pragma unroll
                for (int ni = 0; ni < 4; ni++) mma16816(acc[mi][ni], afr[mi], bfr[ni]);
        }
    }

    // fused LSTM epilogue (cols reordered: col = 4*j + gate)
    bool evenp = !(atg & 1);
#pragma unroll
    for (int mi = 0; mi < 2; mi++) {
#pragma unroll
        for (int ni = 0; ni < 4; ni++) {
            int col = bn * 128 + wn * 32 + ni * 8 + atg * 2;
            float v0 = acc[mi][ni][0] + g_biasSum[col];
            float v1 = acc[mi][ni][1] + g_biasSum[col + 1];
            float v2 = acc[mi][ni][2] + g_biasSum[col];
            float v3 = acc[mi][ni][3] + g_biasSum[col + 1];
            float p0 = __shfl_xor_sync(0xffffffffu, v0, 1);
            float p1 = __shfl_xor_sync(0xffffffffu, v1, 1);
            float p2 = __shfl_xor_sync(0xffffffffu, v2, 1);
            float p3 = __shfl_xor_sync(0xffffffffu, v3, 1);
            if (evenp) {
                int j = col >> 2;
                int r0 = bm * 64 + wm * 32 + mi * 16 + agrp;
#pragma unroll
                for (int rr = 0; rr < 2; rr++) {
                    int r = r0 + rr * 8;
                    float ig = rr ? v2 : v0, fg = rr ? v3 : v1;
                    float gg = rr ? p2 : p0, og = rr ? p3 : p1;
                    float si = sigmoid_f(ig), sf = sigmoid_f(fg);
                    float sg = tanh_precise(gg), so = sigmoid_f(og);
                    float c = g_cstate[r * H_ + j];
                    float cn = sf * c + si * sg;
                    float h = so * tanh_precise(cn);
                    g_cstate[r * H_ + j] = cn;
                    g_xcat[r * 2048 + 1024 + j] = __float2half(h);
                    float m = (float)masks[r * T_ + t];
                    out[((long)r * T_ + t) * H_ + j] = h * m;
                }
            }
        }
    }
}

// ---------------- host launch ----------------
extern "C" void kernel_launch(void* const* d_in, const int* in_sizes, int n_in,
                              void* d_out, int out_size) {
    const float* features   = (const float*)d_in[0];
    const int*   captions   = (const int*)d_in[1];
    const int*   masks      = (const int*)d_in[2];
    const float* img_w      = (const float*)d_in[3];
    const float* init_h_w   = (const float*)d_in[4];
    const float* init_h_b   = (const float*)d_in[5];
    const float* init_c_w   = (const float*)d_in[6];
    const float* init_c_b   = (const float*)d_in[7];
    const float* att_hh_w   = (const float*)d_in[8];
    const float* att_hh_b   = (const float*)d_in[9];
    const float* weight_att = (const float*)d_in[10];
    const float* embedding  = (const float*)d_in[11];
    const float* W_ih       = (const float*)d_in[12];
    const float* W_hh       = (const float*)d_in[13];
    const float* b_ih       = (const float*)d_in[14];
    const float* b_hh       = (const float*)d_in[15];
    float* out = (float*)d_out;

    __half *feat16, *ctx16, *InitH, *InitC, *fmean16, *xcat, *WtImg;
    float *cstate;
    cudaGetSymbolAddress((void**)&feat16,  g_feat16);
    cudaGetSymbolAddress((void**)&ctx16,   g_ctx16);
    cudaGetSymbolAddress((void**)&WtImg,   g_WtImg);
    cudaGetSymbolAddress((void**)&InitH,   g_InitH);
    cudaGetSymbolAddress((void**)&InitC,   g_InitC);
    cudaGetSymbolAddress((void**)&fmean16, g_fmean16);
    cudaGetSymbolAddress((void**)&xcat,    g_xcat);
    cudaGetSymbolAddress((void**)&cstate,  g_cstate);

    cudaFuncSetAttribute(gemm64_ctx, cudaFuncAttributeMaxDynamicSharedMemorySize, GSMEM);

    // one-time phase
    prep_kernel<<<1024, 256>>>(img_w, att_hh_w, init_h_w, init_c_w, W_ih, W_hh,
                               b_ih, b_hh, captions, embedding);
    conv_feat_kernel<<<1024, 256>>>(features);
    fmean_kernel<<<B_, 512>>>();

    // ctx_enc = features @ image_att_w -> fp16  (BK64 GEMM)
    gemm64_ctx<<<dim3(512 / 128, 50176 / 64), 256, GSMEM>>>(
        feat16, 512, WtImg, 512, ctx16, 512, 512);

    // h0 -> xcat h-slice (fp16), c0 -> cstate (fp32)  (BK32 GEMM)
    gemm32_f16<1><<<dim3(1024 / 128, 256 / 64), 256>>>(
        fmean16, 512, InitH, 512, init_h_b, nullptr, xcat + 1024, 2048, 512);
    gemm32_f16<0><<<dim3(1024 / 128, 256 / 64), 256>>>(
        fmean16, 512, InitC, 512, init_c_b, cstate, nullptr, 1024, 512);

    // timestep loop
    for (int t = 0; t < T_; t++) {
        hproj_kernel<<<64, 256>>>(att_hh_b);
        attention_kernel<<<B_, 256>>>(weight_att, t);
        gates_lstm_kernel<<<dim3(32, 4), 256>>>(masks, out, t);
    }
}

// round 15
// speedup vs baseline: 1.2380x; 1.2380x over previous
#include <cuda_runtime.h>
#include <cuda_fp16.h>
#include <cuda_fp8.h>
#include <math.h>

#define B_ 256
#define L_ 196
#define D_ 512
#define H_ 1024
#define E_ 512
#define V_ 10000
#define T_ 20

// ---------------- persistent device scratch ----------------
__device__ __half g_feat16[B_ * L_ * D_];            // fp16 features (ctx GEMM A)
__device__ unsigned char g_feat8[B_ * L_ * D_];      // fp8 features (attention pass2)
__device__ unsigned char g_ctx8 [B_ * L_ * D_];      // fp8 ctx_enc  (attention pass1)
__device__ __half g_WtImg [D_ * D_];                 // image_att_w transposed [e][d]
__device__ __half g_AttHH [D_ * H_];                 // att_hh_w [n=512][k=1024]
__device__ __half g_InitH [H_ * D_];
__device__ __half g_InitC [H_ * D_];
__device__ __half g_Wcat  [4 * H_ * 2 * H_];         // reordered rows n'=4j+g
__device__ float  g_biasSum[4 * H_];                 // reordered b_ih+b_hh
__device__ __half g_embAll[T_ * B_ * E_];            // [t][b][e]
__device__ __half g_fmean16[B_ * D_];
__device__ float  g_hproj  [B_ * D_];
__device__ __half g_xcat   [B_ * 2048];              // [emb | context | h]
__device__ float  g_cstate [B_ * H_];

// ---------------- helpers ----------------
__device__ __forceinline__ float tanh_precise(float x) {
    float ax = fabsf(x);
    float t = __expf(-2.f * ax);
    float r = (1.f - t) / (1.f + t);
    return copysignf(r, x);
}
__device__ __forceinline__ float sigmoid_f(float x) { return 1.f / (1.f + __expf(-x)); }
__device__ __forceinline__ unsigned char f2e4m3(float x) {
    return (unsigned char)__nv_cvt_float_to_fp8(x, __NV_SATFINITE, __NV_E4M3);
}
__device__ __forceinline__ __half2 fp8x2_to_h2(unsigned short s) {
    __half2_raw hr = __nv_cvt_fp8x2_to_halfraw2((__nv_fp8x2_storage_t)s, __NV_E4M3);
    return *reinterpret_cast<__half2*>(&hr);
}
__device__ __forceinline__ float2 fp8x2_to_f2(unsigned short s) {
    return __half22float2(fp8x2_to_h2(s));
}
__device__ __forceinline__ __half2 htanh2(__half2 x) {
    unsigned u = *(unsigned*)&x, r;
    asm("tanh.approx.f16x2 %0, %1;" : "=r"(r) : "r"(u));
    return *(__half2*)&r;
}
__device__ __forceinline__ void cp16(const void* smem_dst, const void* gmem_src) {
    unsigned s = (unsigned)__cvta_generic_to_shared(smem_dst);
    asm volatile("cp.async.cg.shared.global [%0], [%1], 16;\n" :: "r"(s), "l"(gmem_src));
}
__device__ __forceinline__ void cp_commit() { asm volatile("cp.async.commit_group;\n"); }
__device__ __forceinline__ void mma16816(float* c, const unsigned* a, const unsigned* b) {
    asm volatile(
        "mma.sync.aligned.m16n8k16.row.col.f32.f16.f16.f32 "
        "{%0,%1,%2,%3},{%4,%5,%6,%7},{%8,%9},{%0,%1,%2,%3};\n"
        : "+f"(c[0]), "+f"(c[1]), "+f"(c[2]), "+f"(c[3])
        : "r"(a[0]), "r"(a[1]), "r"(a[2]), "r"(a[3]), "r"(b[0]), "r"(b[1]));
}
// ldmatrix x4: 16x16 A tile (row-major, ld in halves), regs in mma A-fragment order
__device__ __forceinline__ void ldm_a(unsigned* r, const __half* base, int ld) {
    int lane = threadIdx.x & 31;
    int sel = lane >> 3, lr = lane & 7;
    const __half* p = base + ((sel & 1) * 8 + lr) * ld + (sel >> 1) * 8;
    unsigned a = (unsigned)__cvta_generic_to_shared(p);
    asm volatile("ldmatrix.sync.aligned.m8n8.x4.shared.b16 {%0,%1,%2,%3}, [%4];"
                 : "=r"(r[0]), "=r"(r[1]), "=r"(r[2]), "=r"(r[3]) : "r"(a));
}
// ldmatrix x4: 16(n)x16(k) B tile
__device__ __forceinline__ void ldm_b(unsigned* r, const __half* base, int ld) {
    int lane = threadIdx.x & 31;
    int sel = lane >> 3, lr = lane & 7;
    const __half* p = base + ((sel >> 1) * 8 + lr) * ld + (sel & 1) * 8;
    unsigned a = (unsigned)__cvta_generic_to_shared(p);
    asm volatile("ldmatrix.sync.aligned.m8n8.x4.shared.b16 {%0,%1,%2,%3}, [%4];"
                 : "=r"(r[0]), "=r"(r[1]), "=r"(r[2]), "=r"(r[3]) : "r"(a));
}

// ---------------- prep kernels (one-time) ----------------
__global__ void prep_kernel(const float* __restrict__ img_w,
                            const float* __restrict__ att_hh_w,
                            const float* __restrict__ init_h_w,
                            const float* __restrict__ init_c_w,
                            const float* __restrict__ W_ih,
                            const float* __restrict__ W_hh,
                            const float* __restrict__ b_ih,
                            const float* __restrict__ b_hh,
                            const int*   __restrict__ captions,
                            const float* __restrict__ embedding) {
    const long n_wt   = (long)D_ * D_;
    const long n_att  = (long)D_ * H_;
    const long n_init = (long)H_ * D_;
    const long n_wcat = 4096L * 2048L;
    const long n_bias = 4096;
    const long n_emb  = (long)T_ * B_ * E_;
    const long total  = n_wt + n_att + 2 * n_init + n_wcat + n_bias + n_emb;
    long stride = (long)gridDim.x * blockDim.x;
    for (long idx = (long)blockIdx.x * blockDim.x + threadIdx.x; idx < total; idx += stride) {
        long i = idx;
        if (i < n_wt) {
            long e = i / D_, d = i % D_;
            g_WtImg[i] = __float2half(img_w[d * D_ + e]);
            continue;
        }
        i -= n_wt;
        if (i < n_att) { g_AttHH[i] = __float2half(att_hh_w[i]); continue; }
        i -= n_att;
        if (i < n_init) { g_InitH[i] = __float2half(init_h_w[i]); continue; }
        i -= n_init;
        if (i < n_init) { g_InitC[i] = __float2half(init_c_w[i]); continue; }
        i -= n_init;
        if (i < n_wcat) {
            long np = i >> 11, k = i & 2047;
            long j = np >> 2, g = np & 3;
            long orig = g * 1024 + j;
            g_Wcat[i] = __float2half(k < H_ ? W_ih[orig * H_ + k] : W_hh[orig * H_ + (k - H_)]);
            continue;
        }
        i -= n_wcat;
        if (i < n_bias) {
            long j = i >> 2, g = i & 3;
            long orig = g * 1024 + j;
            g_biasSum[i] = b_ih[orig] + b_hh[orig];
            continue;
        }
        i -= n_bias;
        {
            long t = i / ((long)B_ * E_);
            long r = i % ((long)B_ * E_);
            long b = r / E_, e = r % E_;
            int cap = captions[b * T_ + t];
            g_embAll[i] = __float2half(embedding[(long)cap * E_ + e]);
        }
    }
}

__global__ void conv_feat_kernel(const float* __restrict__ f) {
    const long n2 = (long)B_ * L_ * D_ / 2;
    const float2* f2 = (const float2*)f;
    __half2* o2 = (__half2*)g_feat16;
    long stride = (long)gridDim.x * blockDim.x;
    for (long i = (long)blockIdx.x * blockDim.x + threadIdx.x; i < n2; i += stride) {
        float2 v = f2[i];
        o2[i] = __floats2half2_rn(v.x, v.y);
        g_feat8[i * 2]     = f2e4m3(v.x);
        g_feat8[i * 2 + 1] = f2e4m3(v.y);
    }
}

// fmean from fp16 features (conv_feat runs first; stream-ordered)
__global__ void fmean_kernel() {
    int b = blockIdx.x;
    int d = threadIdx.x;  // 512 threads
    const __half* p = g_feat16 + (long)b * L_ * D_ + d;
    float acc = 0.f;
#pragma unroll 4
    for (int l = 0; l < L_; l++) acc += __half2float(p[(long)l * D_]);
    g_fmean16[b * D_ + d] = __float2half(acc * (1.0f / L_));
}

// ---------------- BK64/S2 GEMM (ctx only; output fp8) ----------------
#define GSMEM (2 * (64 + 128) * 72 * 2)
__global__ void __launch_bounds__(256) gemm64_ctx(
    const __half* __restrict__ A, int lda,
    const __half* __restrict__ Bm, int ldb,
    unsigned char* __restrict__ C8, int ldc, int K) {
    extern __shared__ __align__(16) char dynsm[];
    __half* As = (__half*)dynsm;          // [2][64][72]
    __half* Bs = As + 2 * 64 * 72;        // [2][128][72]
    const int AST = 64 * 72, BST = 128 * 72;

    int tid = threadIdx.x;
    int lane = tid & 31, warp = tid >> 5;
    int wm = warp & 1, wn = warp >> 1;
    int bm = blockIdx.y, bn = blockIdx.x;

    int rowA = tid >> 3, ch = (tid & 7) * 8;
    const __half* gA0 = A + ((long)bm * 64 + rowA) * lda + ch;
    const __half* gA1 = gA0 + 32L * lda;
    const __half* gB0 = Bm + ((long)bn * 128 + rowA) * ldb + ch;

    float acc[2][4][4];
#pragma unroll
    for (int mi = 0; mi < 2; mi++)
#pragma unroll
        for (int ni = 0; ni < 4; ni++)
#pragma unroll
            for (int q = 0; q < 4; q++) acc[mi][ni][q] = 0.f;

    const int KT = K >> 6;
    cp16(As + rowA * 72 + ch, gA0);
    cp16(As + (rowA + 32) * 72 + ch, gA1);
#pragma unroll
    for (int q = 0; q < 4; q++)
        cp16(Bs + (rowA + q * 32) * 72 + ch, gB0 + (long)q * 32 * ldb);
    cp_commit();

    int agrp = lane >> 2, atg = lane & 3;

    for (int kt = 0; kt < KT; kt++) {
        asm volatile("cp.async.wait_group 0;\n");
        __syncthreads();
        int cur = kt & 1;
        int nxt = kt + 1;
        if (nxt < KT) {
            int nb = nxt & 1;
            int k0 = nxt * 64;
            cp16(As + nb * AST + rowA * 72 + ch, gA0 + k0);
            cp16(As + nb * AST + (rowA + 32) * 72 + ch, gA1 + k0);
#pragma unroll
            for (int q = 0; q < 4; q++)
                cp16(Bs + nb * BST + (rowA + q * 32) * 72 + ch, gB0 + (long)q * 32 * ldb + k0);
            cp_commit();
        }
        __half* cA = As + cur * AST;
        __half* cB = Bs + cur * BST;
#pragma unroll
        for (int kk = 0; kk < 64; kk += 16) {
            unsigned afr[2][4], tb[4], bfr[4][2];
            ldm_a(afr[0], cA + (wm * 32) * 72 + kk, 72);
            ldm_a(afr[1], cA + (wm * 32 + 16) * 72 + kk, 72);
            ldm_b(tb, cB + (wn * 32) * 72 + kk, 72);
            bfr[0][0] = tb[0]; bfr[0][1] = tb[1]; bfr[1][0] = tb[2]; bfr[1][1] = tb[3];
            ldm_b(tb, cB + (wn * 32 + 16) * 72 + kk, 72);
            bfr[2][0] = tb[0]; bfr[2][1] = tb[1]; bfr[3][0] = tb[2]; bfr[3][1] = tb[3];
#pragma unroll
            for (int mi = 0; mi < 2; mi++)
#pragma unroll
                for (int ni = 0; ni < 4; ni++) mma16816(acc[mi][ni], afr[mi], bfr[ni]);
        }
    }

#pragma unroll
    for (int mi = 0; mi < 2; mi++) {
#pragma unroll
        for (int ni = 0; ni < 4; ni++) {
            int row = bm * 64 + wm * 32 + mi * 16 + agrp;
            int col = bn * 128 + wn * 32 + ni * 8 + atg * 2;
            C8[(long)row * ldc + col]           = f2e4m3(acc[mi][ni][0]);
            C8[(long)row * ldc + col + 1]       = f2e4m3(acc[mi][ni][1]);
            C8[(long)(row + 8) * ldc + col]     = f2e4m3(acc[mi][ni][2]);
            C8[(long)(row + 8) * ldc + col + 1] = f2e4m3(acc[mi][ni][3]);
        }
    }
}

// ---------------- BK32/S3 GEMM (h0/c0), R7-proven numerics ----------------
// OUT: 0 = fp32 Cf, 1 = fp16 Ch
template <int OUT>
__global__ void __launch_bounds__(256) gemm32_f16(
    const __half* __restrict__ A, int lda,
    const __half* __restrict__ Bm, int ldb,
    const float* __restrict__ bias,
    float* __restrict__ Cf, __half* __restrict__ Ch, int ldc, int K) {
    const int S = 3;
    __shared__ __align__(16) __half As[S][64][40];
    __shared__ __align__(16) __half Bs[S][128][40];

    int tid = threadIdx.x;
    int lane = tid & 31, warp = tid >> 5;
    int wm = warp & 1, wn = warp >> 1;
    int bm = blockIdx.y, bn = blockIdx.x;

    const __half* gA  = A  + ((long)bm * 64  + (tid >> 2)) * lda + (tid & 3) * 8;
    const __half* gB0 = Bm + ((long)bn * 128 + (tid >> 2)) * ldb + (tid & 3) * 8;
    const __half* gB1 = gB0 + 64L * ldb;

    __half* sA  = &As[0][tid >> 2][(tid & 3) * 8];
    __half* sB0 = &Bs[0][tid >> 2][(tid & 3) * 8];
    __half* sB1 = sB0 + 64 * 40;
    const int ABUF = 64 * 40;
    const int BBUF = 128 * 40;

    float acc[2][4][4];
#pragma unroll
    for (int mi = 0; mi < 2; mi++)
#pragma unroll
        for (int ni = 0; ni < 4; ni++)
#pragma unroll
            for (int q = 0; q < 4; q++) acc[mi][ni][q] = 0.f;

    const int KT = K >> 5;
#pragma unroll
    for (int s = 0; s < S - 1; s++) {
        if (s < KT) {
            cp16(sA + s * ABUF, gA + s * 32);
            cp16(sB0 + s * BBUF, gB0 + s * 32);
            cp16(sB1 + s * BBUF, gB1 + s * 32);
        }
        cp_commit();
    }

    int agrp = lane >> 2, atg = lane & 3;

    for (int kt = 0; kt < KT; kt++) {
        asm volatile("cp.async.wait_group %0;\n" :: "n"(S - 2));
        __syncthreads();
        int nxt = kt + S - 1;
        if (nxt < KT) {
            int nb = nxt % S;
            cp16(sA + nb * ABUF, gA + nxt * 32);
            cp16(sB0 + nb * BBUF, gB0 + nxt * 32);
            cp16(sB1 + nb * BBUF, gB1 + nxt * 32);
        }
        cp_commit();
        int cur = kt % S;
#pragma unroll
        for (int kk = 0; kk < 32; kk += 16) {
            unsigned afr[2][4], tb[4], bfr[4][2];
            ldm_a(afr[0], &As[cur][wm * 32][kk], 40);
            ldm_a(afr[1], &As[cur][wm * 32 + 16][kk], 40);
            ldm_b(tb, &Bs[cur][wn * 32][kk], 40);
            bfr[0][0] = tb[0]; bfr[0][1] = tb[1]; bfr[1][0] = tb[2]; bfr[1][1] = tb[3];
            ldm_b(tb, &Bs[cur][wn * 32 + 16][kk], 40);
            bfr[2][0] = tb[0]; bfr[2][1] = tb[1]; bfr[3][0] = tb[2]; bfr[3][1] = tb[3];
#pragma unroll
            for (int mi = 0; mi < 2; mi++)
#pragma unroll
                for (int ni = 0; ni < 4; ni++) mma16816(acc[mi][ni], afr[mi], bfr[ni]);
        }
    }

#pragma unroll
    for (int mi = 0; mi < 2; mi++) {
#pragma unroll
        for (int ni = 0; ni < 4; ni++) {
            int row = bm * 64 + wm * 32 + mi * 16 + agrp;
            int col = bn * 128 + wn * 32 + ni * 8 + atg * 2;
            float bv0 = bias ? bias[col] : 0.f;
            float bv1 = bias ? bias[col + 1] : 0.f;
            float v00 = acc[mi][ni][0] + bv0, v01 = acc[mi][ni][1] + bv1;
            float v10 = acc[mi][ni][2] + bv0, v11 = acc[mi][ni][3] + bv1;
            if (OUT == 1) {
                Ch[(long)row * ldc + col]           = __float2half(v00);
                Ch[(long)row * ldc + col + 1]       = __float2half(v01);
                Ch[(long)(row + 8) * ldc + col]     = __float2half(v10);
                Ch[(long)(row + 8) * ldc + col + 1] = __float2half(v11);
            } else {
                Cf[(long)row * ldc + col]           = v00;
                Cf[(long)row * ldc + col + 1]       = v01;
                Cf[(long)(row + 8) * ldc + col]     = v10;
                Cf[(long)(row + 8) * ldc + col + 1] = v11;
            }
        }
    }
}

// ---------------- hproj: [256,512] = h @ AttHH^T + b ; 64 CTAs, tile 16x128, BK=64 ----------------
__global__ void __launch_bounds__(256) hproj_kernel(const float* __restrict__ att_b) {
    const int LDSH = 72;
    __shared__ __align__(16) __half hA[2][16][LDSH];
    __shared__ __align__(16) __half hB[2][128][LDSH];
    int tid = threadIdx.x;
    int lane = tid & 31, warp = tid >> 5;
    int cta = blockIdx.x;
    int m0 = (cta >> 2) * 16, n0 = (cta & 3) * 128;

    float acc[2][4];
#pragma unroll
    for (int ni = 0; ni < 2; ni++)
#pragma unroll
        for (int q = 0; q < 4; q++) acc[ni][q] = 0.f;

    const __half* gA = g_xcat + (m0 + (tid >> 3)) * 2048 + 1024 + (tid & 7) * 8;  // tid<128
    const int KT = 1024 / 64;
    if (tid < 128) cp16(&hA[0][tid >> 3][(tid & 7) * 8], gA);
#pragma unroll
    for (int q = 0; q < 4; q++) {
        int idx = tid + 256 * q;
        int row = idx >> 3, ch = idx & 7;
        cp16(&hB[0][row][ch * 8], g_AttHH + (n0 + row) * 1024 + ch * 8);
    }
    cp_commit();

    for (int kt = 0; kt < KT; kt++) {
        asm volatile("cp.async.wait_group 0;\n");
        __syncthreads();
        int cur = kt & 1;
        int nxt = kt + 1;
        if (nxt < KT) {
            int nb = nxt & 1;
            if (tid < 128) cp16(&hA[nb][tid >> 3][(tid & 7) * 8], gA + nxt * 64);
#pragma unroll
            for (int q = 0; q < 4; q++) {
                int idx = tid + 256 * q;
                int row = idx >> 3, ch = idx & 7;
                cp16(&hB[nb][row][ch * 8], g_AttHH + (n0 + row) * 1024 + nxt * 64 + ch * 8);
            }
        }
        cp_commit();
#pragma unroll
        for (int kk = 0; kk < 64; kk += 16) {
            unsigned afr[4], tb[4], bfr[2][2];
            ldm_a(afr, &hA[cur][0][kk], LDSH);
            ldm_b(tb, &hB[cur][warp * 16][kk], LDSH);
            bfr[0][0] = tb[0]; bfr[0][1] = tb[1]; bfr[1][0] = tb[2]; bfr[1][1] = tb[3];
            mma16816(acc[0], afr, bfr[0]);
            mma16816(acc[1], afr, bfr[1]);
        }
        __syncthreads();
    }
    int r = lane >> 2, cf = (lane & 3) * 2;
#pragma unroll
    for (int ni = 0; ni < 2; ni++) {
        int n = n0 + warp * 16 + ni * 8 + cf;
        float b0 = att_b[n], b1 = att_b[n + 1];
        g_hproj[(m0 + r) * 512 + n]         = acc[ni][0] + b0;
        g_hproj[(m0 + r) * 512 + n + 1]     = acc[ni][1] + b1;
        g_hproj[(m0 + r + 8) * 512 + n]     = acc[ni][2] + b0;
        g_hproj[(m0 + r + 8) * 512 + n + 1] = acc[ni][3] + b1;
    }
}

// ---------------- attention: fp8 ctx + f16x2 score math ; fp8/fp32 context pass ----------------
__global__ void __launch_bounds__(256) attention_kernel(const float* __restrict__ watt, int t) {
    int b = blockIdx.x;
    int tid = threadIdx.x, lane = tid & 31, warp = tid >> 5;
    __shared__ float sc[L_], alph[L_], red[256];

    // copy this step's embedding into xcat emb slice
    {
        const __half* src = g_embAll + ((long)t * B_ + b) * E_;
        for (int k = tid; k < E_; k += 256) g_xcat[b * 2048 + k] = src[k];
    }

    // per-lane fixed 16-d slice as half2 pairs (hproj fp32 -> half2 on load)
    __half2 hp2[8], w2[8];
#pragma unroll
    for (int q = 0; q < 8; q++) {
        int d = lane * 16 + q * 2;
        hp2[q] = __floats2half2_rn(g_hproj[b * D_ + d], g_hproj[b * D_ + d + 1]);
        w2[q]  = __floats2half2_rn(watt[d], watt[d + 1]);
    }

    // pass 1: scores over L (fp8 ctx, f16x2 math: HADD2 + tanh.f16x2 + HFMA2)
    const unsigned* crow_base = (const unsigned*)(g_ctx8 + (long)b * L_ * D_);
    for (int l = warp; l < L_; l += 8) {
        const unsigned* cr = crow_base + l * (D_ / 4) + lane * 4;
        __half2 a2 = __float2half2_rn(0.f);
#pragma unroll
        for (int q = 0; q < 4; q++) {
            unsigned u = cr[q];
            __half2 lo = fp8x2_to_h2((unsigned short)(u & 0xffff));
            __half2 hi = fp8x2_to_h2((unsigned short)(u >> 16));
            a2 = __hfma2(htanh2(__hadd2(lo, hp2[q * 2])),     w2[q * 2],     a2);
            a2 = __hfma2(htanh2(__hadd2(hi, hp2[q * 2 + 1])), w2[q * 2 + 1], a2);
        }
        float2 fr = __half22float2(a2);
        float acc = fr.x + fr.y;
#pragma unroll
        for (int o = 16; o; o >>= 1) acc += __shfl_xor_sync(0xffffffffu, acc, o);
        if (lane == 0) sc[l] = acc;
    }
    __syncthreads();

    // softmax over L (fp32)
    float v = (tid < L_) ? sc[tid] : -3e38f;
    red[tid] = v;
    __syncthreads();
#pragma unroll
    for (int s = 128; s; s >>= 1) {
        if (tid < s) red[tid] = fmaxf(red[tid], red[tid + s]);
        __syncthreads();
    }
    float mx = red[0];
    __syncthreads();
    float e = (tid < L_) ? __expf(v - mx) : 0.f;
    red[tid] = e;
    __syncthreads();
#pragma unroll
    for (int s = 128; s; s >>= 1) {
        if (tid < s) red[tid] += red[tid + s];
        __syncthreads();
    }
    float inv = 1.f / red[0];
    if (tid < L_) alph[tid] = e * inv;
    __syncthreads();

    // pass 2: context from fp8 features (fp32 accumulation — proven path)
    const unsigned char* fbase = g_feat8 + (long)b * L_ * D_ + tid * 2;
    float a0 = 0.f, a1 = 0.f;
#pragma unroll 4
    for (int l = 0; l < L_; l++) {
        unsigned short u = *(const unsigned short*)(fbase + (long)l * D_);
        float2 f2 = fp8x2_to_f2(u);
        float al = alph[l];
        a0 = fmaf(al, f2.x, a0);
        a1 = fmaf(al, f2.y, a1);
    }
    __half* dst = g_xcat + b * 2048 + 512 + tid * 2;
    dst[0] = __float2half(a0 * (1.0f / L_));
    dst[1] = __float2half(a1 * (1.0f / L_));
}

// ---------------- gates GEMM [256,4096] K=2048, BK32/S3 + fused LSTM (R7-proven) ----------------
__global__ void __launch_bounds__(256) gates_lstm_kernel(
    const int* __restrict__ masks, float* __restrict__ out, int t) {
    const int S = 3;
    __shared__ __align__(16) __half As[S][64][40];
    __shared__ __align__(16) __half Bs[S][128][40];

    int tid = threadIdx.x;
    int lane = tid & 31, warp = tid >> 5;
    int wm = warp & 1, wn = warp >> 1;
    int bm = blockIdx.y, bn = blockIdx.x;
    const int K = 2048;

    const __half* gA  = g_xcat + ((long)bm * 64  + (tid >> 2)) * 2048 + (tid & 3) * 8;
    const __half* gB0 = g_Wcat + ((long)bn * 128 + (tid >> 2)) * 2048 + (tid & 3) * 8;
    const __half* gB1 = gB0 + 64L * 2048;

    __half* sA  = &As[0][tid >> 2][(tid & 3) * 8];
    __half* sB0 = &Bs[0][tid >> 2][(tid & 3) * 8];
    __half* sB1 = sB0 + 64 * 40;
    const int ABUF = 64 * 40;
    const int BBUF = 128 * 40;

    float acc[2][4][4];
#pragma unroll
    for (int mi = 0; mi < 2; mi++)
#pragma unroll
        for (int ni = 0; ni < 4; ni++)
#pragma unroll
            for (int q = 0; q < 4; q++) acc[mi][ni][q] = 0.f;

    const int KT = K >> 5;
#pragma unroll
    for (int s = 0; s < S - 1; s++) {
        cp16(sA + s * ABUF, gA + s * 32);
        cp16(sB0 + s * BBUF, gB0 + s * 32);
        cp16(sB1 + s * BBUF, gB1 + s * 32);
        cp_commit();
    }

    int agrp = lane >> 2, atg = lane & 3;

    for (int kt = 0; kt < KT; kt++) {
        asm volatile("cp.async.wait_group %0;\n" :: "n"(S - 2));
        __syncthreads();
        int nxt = kt + S - 1;
        if (nxt < KT) {
            int nb = nxt % S;
            cp16(sA + nb * ABUF, gA + nxt * 32);
            cp16(sB0 + nb * BBUF, gB0 + nxt * 32);
            cp16(sB1 + nb * BBUF, gB1 + nxt * 32);
        }
        cp_commit();
        int cur = kt % S;
#pragma unroll
        for (int kk = 0; kk < 32; kk += 16) {
            unsigned afr[2][4], tb[4], bfr[4][2];
            ldm_a(afr[0], &As[cur][wm * 32][kk], 40);
            ldm_a(afr[1], &As[cur][wm * 32 + 16][kk], 40);
            ldm_b(tb, &Bs[cur][wn * 32][kk], 40);
            bfr[0][0] = tb[0]; bfr[0][1] = tb[1]; bfr[1][0] = tb[2]; bfr[1][1] = tb[3];
            ldm_b(tb, &Bs[cur][wn * 32 + 16][kk], 40);
            bfr[2][0] = tb[0]; bfr[2][1] = tb[1]; bfr[3][0] = tb[2]; bfr[3][1] = tb[3];
#pragma unroll
            for (int mi = 0; mi < 2; mi++)
#pragma unroll
                for (int ni = 0; ni < 4; ni++) mma16816(acc[mi][ni], afr[mi], bfr[ni]);
        }
    }

    // fused LSTM epilogue (cols reordered: col = 4*j + gate)
    bool evenp = !(atg & 1);
#pragma unroll
    for (int mi = 0; mi < 2; mi++) {
#pragma unroll
        for (int ni = 0; ni < 4; ni++) {
            int col = bn * 128 + wn * 32 + ni * 8 + atg * 2;
            float v0 = acc[mi][ni][0] + g_biasSum[col];
            float v1 = acc[mi][ni][1] + g_biasSum[col + 1];
            float v2 = acc[mi][ni][2] + g_biasSum[col];
            float v3 = acc[mi][ni][3] + g_biasSum[col + 1];
            float p0 = __shfl_xor_sync(0xffffffffu, v0, 1);
            float p1 = __shfl_xor_sync(0xffffffffu, v1, 1);
            float p2 = __shfl_xor_sync(0xffffffffu, v2, 1);
            float p3 = __shfl_xor_sync(0xffffffffu, v3, 1);
            if (evenp) {
                int j = col >> 2;
                int r0 = bm * 64 + wm * 32 + mi * 16 + agrp;
#pragma unroll
                for (int rr = 0; rr < 2; rr++) {
                    int r = r0 + rr * 8;
                    float ig = rr ? v2 : v0, fg = rr ? v3 : v1;
                    float gg = rr ? p2 : p0, og = rr ? p3 : p1;
                    float si = sigmoid_f(ig), sf = sigmoid_f(fg);
                    float sg = tanh_precise(gg), so = sigmoid_f(og);
                    float c = g_cstate[r * H_ + j];
                    float cn = sf * c + si * sg;
                    float h = so * tanh_precise(cn);
                    g_cstate[r * H_ + j] = cn;
                    g_xcat[r * 2048 + 1024 + j] = __float2half(h);
                    float m = (float)masks[r * T_ + t];
                    out[((long)r * T_ + t) * H_ + j] = h * m;
                }
            }
        }
    }
}

// ---------------- host launch ----------------
extern "C" void kernel_launch(void* const* d_in, const int* in_sizes, int n_in,
                              void* d_out, int out_size) {
    const float* features   = (const float*)d_in[0];
    const int*   captions   = (const int*)d_in[1];
    const int*   masks      = (const int*)d_in[2];
    const float* img_w      = (const float*)d_in[3];
    const float* init_h_w   = (const float*)d_in[4];
    const float* init_h_b   = (const float*)d_in[5];
    const float* init_c_w   = (const float*)d_in[6];
    const float* init_c_b   = (const float*)d_in[7];
    const float* att_hh_w   = (const float*)d_in[8];
    const float* att_hh_b   = (const float*)d_in[9];
    const float* weight_att = (const float*)d_in[10];
    const float* embedding  = (const float*)d_in[11];
    const float* W_ih       = (const float*)d_in[12];
    const float* W_hh       = (const float*)d_in[13];
    const float* b_ih       = (const float*)d_in[14];
    const float* b_hh       = (const float*)d_in[15];
    float* out = (float*)d_out;

    __half *feat16, *InitH, *InitC, *fmean16, *xcat, *WtImg;
    unsigned char *ctx8;
    float *cstate;
    cudaGetSymbolAddress((void**)&feat16,  g_feat16);
    cudaGetSymbolAddress((void**)&ctx8,    g_ctx8);
    cudaGetSymbolAddress((void**)&WtImg,   g_WtImg);
    cudaGetSymbolAddress((void**)&InitH,   g_InitH);
    cudaGetSymbolAddress((void**)&InitC,   g_InitC);
    cudaGetSymbolAddress((void**)&fmean16, g_fmean16);
    cudaGetSymbolAddress((void**)&xcat,    g_xcat);
    cudaGetSymbolAddress((void**)&cstate,  g_cstate);

    cudaFuncSetAttribute(gemm64_ctx, cudaFuncAttributeMaxDynamicSharedMemorySize, GSMEM);

    // one-time phase
    prep_kernel<<<1024, 256>>>(img_w, att_hh_w, init_h_w, init_c_w, W_ih, W_hh,
                               b_ih, b_hh, captions, embedding);
    conv_feat_kernel<<<1024, 256>>>(features);
    fmean_kernel<<<B_, 512>>>();

    // ctx_enc = features @ image_att_w -> fp8  (BK64 GEMM)
    gemm64_ctx<<<dim3(512 / 128, 50176 / 64), 256, GSMEM>>>(
        feat16, 512, WtImg, 512, ctx8, 512, 512);

    // h0 -> xcat h-slice (fp16), c0 -> cstate (fp32)  (BK32 GEMM)
    gemm32_f16<1><<<dim3(1024 / 128, 256 / 64), 256>>>(
        fmean16, 512, InitH, 512, init_h_b, nullptr, xcat + 1024, 2048, 512);
    gemm32_f16<0><<<dim3(1024 / 128, 256 / 64), 256>>>(
        fmean16, 512, InitC, 512, init_c_b, cstate, nullptr, 1024, 512);

    // timestep loop
    for (int t = 0; t < T_; t++) {
        hproj_kernel<<<64, 256>>>(att_hh_b);
        attention_kernel<<<B_, 256>>>(weight_att, t);
        gates_lstm_kernel<<<dim3(32, 4), 256>>>(masks, out, t);
    }
}